// round 9
// baseline (speedup 1.0000x reference)
#include <cuda_runtime.h>
#include <cuda_pipeline_primitives.h>

// Problem dims (fixed)
#define T_DIM 100
#define B_DIM 128
#define F_DIM 4096
#define C_DIM 10

#define ROWS_PER_BLOCK 8             // consecutive (t,b) rows per block (same t)
#define RPAIRS (ROWS_PER_BLOCK / 2)
#define THREADS_K1 64                // 2 warps
#define CHUNK_F4 64                  // float4 per row per chunk (= THREADS_K1)
#define F4_DIM (F_DIM / 4)           // 1024
#define N_CHUNKS (F4_DIM / CHUNK_F4) // 16
#define STAGES 3                     // 3 x 16KB = 48KB static smem
#define OUTS (ROWS_PER_BLOCK * C_DIM) // 80 outputs per block
#define BC (B_DIM * C_DIM)           // 1280

typedef unsigned long long u64;

// Packed f32x2 ops (Blackwell): one fma-pipe instruction, two fp32 lanes.
__device__ __forceinline__ u64 mul2(u64 a, u64 b) {
    u64 d; asm("mul.rn.f32x2 %0, %1, %2;" : "=l"(d) : "l"(a), "l"(b)); return d;
}
__device__ __forceinline__ u64 fma2(u64 a, u64 b, u64 c) {
    u64 d; asm("fma.rn.f32x2 %0, %1, %2, %3;" : "=l"(d) : "l"(a), "l"(b), "l"(c)); return d;
}
__device__ __forceinline__ u64 pack2(float lo, float hi) {
    u64 d; asm("mov.b64 %0, {%1, %2};" : "=l"(d) : "f"(lo), "f"(hi)); return d;
}
__device__ __forceinline__ void unpack2(u64 p, float& lo, float& hi) {
    asm("mov.b64 {%0, %1}, %2;" : "=f"(lo), "=f"(hi) : "l"(p));
}

// Scratch for current, TRANSPOSED: g_currentT[(b*C + c) * T + t]  (512 KB)
__device__ float g_currentT[BC * T_DIM];

// ============================ Kernel 1: GEMV ============================
// current[t,b,c] = 2 * sum_f spike*mask*W[c,f] + bias[c]
// cp.async 3-stage smem pipeline decouples stream depth from registers.
// Each thread consumes only its own cp.async'd bytes -> no barriers in loop.
__global__ __launch_bounds__(THREADS_K1)
void snn_gemv_kernel(const float* __restrict__ spike,
                     const float* __restrict__ mask,
                     const float* __restrict__ W,
                     const float* __restrict__ bias)
{
    // [stage][arr(spike=0,mask=1)][row][f4] = 3*2*8*64*16B = 48KB exactly
    __shared__ float4 pipe[STAGES][2][ROWS_PER_BLOCK][CHUNK_F4];

    const int row0 = blockIdx.x * ROWS_PER_BLOCK;
    const int tid  = threadIdx.x;

    const float4* sp = reinterpret_cast<const float4*>(spike) + (size_t)row0 * F4_DIM;
    const float4* mk = reinterpret_cast<const float4*>(mask)  + (size_t)row0 * F4_DIM;
    const float4* W4 = reinterpret_cast<const float4*>(W);

    // Issue one chunk's loads into a stage (this thread's column only).
    auto issue = [&](int stage, int chunk) {
        const int f4 = chunk * CHUNK_F4 + tid;
#pragma unroll
        for (int r = 0; r < ROWS_PER_BLOCK; ++r) {
            __pipeline_memcpy_async(&pipe[stage][0][r][tid], &sp[(size_t)r * F4_DIM + f4], 16);
            __pipeline_memcpy_async(&pipe[stage][1][r][tid], &mk[(size_t)r * F4_DIM + f4], 16);
        }
    };

    u64 acc2[RPAIRS][C_DIM];   // lo lane = row 2rp, hi lane = row 2rp+1
#pragma unroll
    for (int rp = 0; rp < RPAIRS; ++rp)
#pragma unroll
        for (int c = 0; c < C_DIM; ++c)
            acc2[rp][c] = 0ull;

    // Prologue: fill STAGES-1 stages.
#pragma unroll
    for (int s = 0; s < STAGES - 1; ++s) {
        issue(s, s);
        __pipeline_commit();
    }

#pragma unroll 4
    for (int k = 0; k < N_CHUNKS; ++k) {
        const int nc = k + STAGES - 1;
        if (nc < N_CHUNKS) issue(nc % STAGES, nc);
        __pipeline_commit();                 // possibly-empty group keeps count uniform
        __pipeline_wait_prior(STAGES - 1);   // chunk k's data is ready

        const int st = k % STAGES;
        const int f4 = k * CHUNK_F4 + tid;

        // Build packed x pairs from smem (thread-private columns).
        u64 x[RPAIRS][4];
#pragma unroll
        for (int rp = 0; rp < RPAIRS; ++rp) {
            const float4 sa = pipe[st][0][2 * rp][tid];
            const float4 sb = pipe[st][0][2 * rp + 1][tid];
            const float4 ma = pipe[st][1][2 * rp][tid];
            const float4 mb = pipe[st][1][2 * rp + 1][tid];
            x[rp][0] = mul2(pack2(sa.x, sb.x), pack2(ma.x, mb.x));
            x[rp][1] = mul2(pack2(sa.y, sb.y), pack2(ma.y, mb.y));
            x[rp][2] = mul2(pack2(sa.z, sb.z), pack2(ma.z, mb.z));
            x[rp][3] = mul2(pack2(sa.w, sb.w), pack2(ma.w, mb.w));
        }

        // 10 W float4 loads per chunk amortized across 8 rows (L1-resident:
        // cp.async.cg bypasses L1, so the stream never evicts W).
#pragma unroll
        for (int c = 0; c < C_DIM; ++c) {
            const float4 wv = __ldg(&W4[(size_t)c * F4_DIM + f4]);
            const u64 w0 = pack2(wv.x, wv.x);
            const u64 w1 = pack2(wv.y, wv.y);
            const u64 w2 = pack2(wv.z, wv.z);
            const u64 w3 = pack2(wv.w, wv.w);
#pragma unroll
            for (int rp = 0; rp < RPAIRS; ++rp) {
                u64 a = acc2[rp][c];
                a = fma2(x[rp][0], w0, a);
                a = fma2(x[rp][1], w1, a);
                a = fma2(x[rp][2], w2, a);
                a = fma2(x[rp][3], w3, a);
                acc2[rp][c] = a;
            }
        }
    }

    // Reduction. sred aliases the (now dead) pipe buffer to stay at 48KB.
    __syncthreads();   // everyone done reading pipe before aliasing
    float* sred = reinterpret_cast<float*>(pipe);  // [2 warps][80]
    const int lane = tid & 31;
    const int warp = tid >> 5;

#pragma unroll
    for (int rp = 0; rp < RPAIRS; ++rp) {
#pragma unroll
        for (int c = 0; c < C_DIM; ++c) {
            float vlo, vhi;
            unpack2(acc2[rp][c], vlo, vhi);
#pragma unroll
            for (int o = 16; o > 0; o >>= 1) {
                vlo += __shfl_down_sync(0xffffffffu, vlo, o);
                vhi += __shfl_down_sync(0xffffffffu, vhi, o);
            }
            if (lane == 0) {
                sred[warp * OUTS + (2 * rp) * C_DIM + c]     = vlo;
                sred[warp * OUTS + (2 * rp + 1) * C_DIM + c] = vhi;
            }
        }
    }
    __syncthreads();

    // FIX (R7 bug): 80 outputs, 64 threads -> strided loop, not `if (tid<80)`.
#pragma unroll
    for (int o = tid; o < OUTS; o += THREADS_K1) {
        float s = sred[o] + sred[OUTS + o];
        const int r = o / C_DIM;
        const int c = o % C_DIM;
        const int row = row0 + r;
        const int t = row / B_DIM;
        const int b = row % B_DIM;
        // 2.0f = 1/keep (dropout); bias added once. Transposed store.
        g_currentT[(size_t)(b * C_DIM + c) * T_DIM + t] = 2.0f * s + bias[c];
    }
}

// ============================ Kernel 2: scan ============================
// Proven R4 form (7.0us): 40 blocks x 32 threads, batch all 25 float4 loads
// up front (MLP=25), then run the serial LIF chain from registers/L1.
__global__ __launch_bounds__(32)
void snn_scan_kernel(float* __restrict__ out)
{
    const int idx = blockIdx.x * 32 + threadIdx.x;  // 0..1279
    if (idx >= BC) return;

    const float4* cur4 = reinterpret_cast<const float4*>(g_currentT + (size_t)idx * T_DIM);

    float vals[T_DIM];
#pragma unroll
    for (int i = 0; i < T_DIM / 4; ++i) {
        const float4 c4 = cur4[i];
        vals[4 * i + 0] = c4.x;
        vals[4 * i + 1] = c4.y;
        vals[4 * i + 2] = c4.z;
        vals[4 * i + 3] = c4.w;
    }

    float v = 0.0f;
#pragma unroll
    for (int t = 0; t < T_DIM; ++t) {
        v = 0.9f * v + vals[t];
        const float s = (v - 1.0f) > 0.0f ? 1.0f : 0.0f;
        out[(size_t)t * BC + idx] = s;   // coalesced across threads
        v -= s;
    }
}

extern "C" void kernel_launch(void* const* d_in, const int* in_sizes, int n_in,
                              void* d_out, int out_size)
{
    const float* spike = (const float*)d_in[0];  // [T,B,F]
    const float* mask  = (const float*)d_in[1];  // [T,B,F]
    const float* W     = (const float*)d_in[2];  // [C,F]
    const float* bias  = (const float*)d_in[3];  // [C]
    float* out = (float*)d_out;                  // [T,B,C]

    const int grid1 = (T_DIM * B_DIM) / ROWS_PER_BLOCK;  // 1600

    snn_gemv_kernel<<<grid1, THREADS_K1>>>(spike, mask, W, bias);

    snn_scan_kernel<<<BC / 32, 32>>>(out);               // 40 blocks x 32 thr
}